// round 14
// baseline (speedup 1.0000x reference)
#include <cuda_runtime.h>
#include <cuda_fp16.h>
#include <cstdint>
#include <math.h>

// ---------------- problem constants ----------------
#define Bn   4
#define Tn   2048
#define Cn   1024
#define Hn   16
#define HSn  64
#define DFFn 4096
#define Mn   (Bn*Tn)          // 8192

// GEMM-operand layout: __half, K-major, each 64-half K-chunk p64-permuted.

// ---------------- scratch (__device__ globals; allocation-free) ------------
__device__ __half g_buf0[(size_t)Mn*Cn];        // ln1 / attn-y / ln2 (half, permuted)
__device__ __half g_qkv [(size_t)Mn*3*Cn];      // merged q|k|v (half, PLAIN)
__device__ float  g_x2  [(size_t)Mn*Cn];        // x + attn (fp32, plain)
__device__ __half g_ff  [(size_t)Mn*DFFn];      // relu(h@W1+b1) (half, permuted)
__device__ __half g_wtqkv[(size_t)3*Cn*Cn];     // (Wq|Wk|Wv)^T (half, permuted)
__device__ __half g_wto [(size_t)Cn*Cn];        // Wo^T
__device__ __half g_wt1 [(size_t)DFFn*Cn];      // W1^T
__device__ __half g_wt2 [(size_t)Cn*DFFn];      // W2^T
__device__ float  g_bqkv[3*Cn];

// ---------------- helpers ----------------
__device__ __forceinline__ uint32_t smem_u32(const void* p) {
    uint32_t a;
    asm("{ .reg .u64 t; cvta.to.shared.u64 t, %1; cvt.u32.u64 %0, t; }" : "=r"(a) : "l"(p));
    return a;
}
__device__ __forceinline__ int p64(int c) {
    int ks = c >> 4, cc = c & 15;
    int kp = ks >> 1, sp = ks & 1;
    int t4 = (cc >> 1) & 3, hi = (cc >> 3) & 1, j = c & 1;
    return (2*t4 + kp)*8 + sp*4 + hi*2 + j;
}
__device__ __forceinline__ float ex2f(float x) {
    float r; asm("ex2.approx.f32 %0, %1;" : "=f"(r) : "f"(x)); return r;
}

#define CP16(dst, src) \
    asm volatile("cp.async.cg.shared.global [%0], [%1], 16;" :: "r"(dst), "l"(src))
#define CPCOMMIT() asm volatile("cp.async.commit_group;")
#define CPWAIT1()  asm volatile("cp.async.wait_group 1;" ::: "memory")
#define CPWAIT2()  asm volatile("cp.async.wait_group 2;" ::: "memory")
#define CPWAIT0()  asm volatile("cp.async.wait_group 0;" ::: "memory")

__device__ __forceinline__ void mma16(float* d, uint32_t a0, uint32_t a1,
                                      uint32_t a2, uint32_t a3,
                                      uint32_t b0, uint32_t b1) {
    asm volatile("mma.sync.aligned.m16n8k16.row.col.f32.f16.f16.f32 "
        "{%0,%1,%2,%3}, {%4,%5,%6,%7}, {%8,%9}, {%0,%1,%2,%3};"
        : "+f"(d[0]), "+f"(d[1]), "+f"(d[2]), "+f"(d[3])
        : "r"(a0), "r"(a1), "r"(a2), "r"(a3), "r"(b0), "r"(b1));
}
__device__ __forceinline__ void ldsm4(uint32_t& r0, uint32_t& r1, uint32_t& r2,
                                      uint32_t& r3, uint32_t a) {
    asm volatile("ldmatrix.sync.aligned.m8n8.x4.shared.b16 {%0,%1,%2,%3}, [%4];"
        : "=r"(r0), "=r"(r1), "=r"(r2), "=r"(r3) : "r"(a));
}
__device__ __forceinline__ void ldsm4t(uint32_t& r0, uint32_t& r1, uint32_t& r2,
                                       uint32_t& r3, uint32_t a) {
    asm volatile("ldmatrix.sync.aligned.m8n8.x4.trans.shared.b16 {%0,%1,%2,%3}, [%4];"
        : "=r"(r0), "=r"(r1), "=r"(r2), "=r"(r3) : "r"(a));
}

// ---------------- LayerNorm -> half permuted --------------------------------
__global__ void ln_kernel(const float* __restrict__ x, const float* __restrict__ g,
                          const float* __restrict__ be, __half* __restrict__ out) {
    __shared__ float sh1[8], sh2[8];
    const int row = blockIdx.x;
    const int t = threadIdx.x;
    float4 v = ((const float4*)(x + (size_t)row * Cn))[t];

    float s = v.x + v.y + v.z + v.w;
    #pragma unroll
    for (int o = 16; o; o >>= 1) s += __shfl_down_sync(0xffffffffu, s, o);
    if ((t & 31) == 0) sh1[t >> 5] = s;
    __syncthreads();
    float mu = (sh1[0]+sh1[1]+sh1[2]+sh1[3]+sh1[4]+sh1[5]+sh1[6]+sh1[7]) * (1.0f/Cn);

    float dx = v.x-mu, dy = v.y-mu, dz = v.z-mu, dw = v.w-mu;
    float ss = dx*dx + dy*dy + dz*dz + dw*dw;
    #pragma unroll
    for (int o = 16; o; o >>= 1) ss += __shfl_down_sync(0xffffffffu, ss, o);
    if ((t & 31) == 0) sh2[t >> 5] = ss;
    __syncthreads();
    float rstd = rsqrtf((sh2[0]+sh2[1]+sh2[2]+sh2[3]+sh2[4]+sh2[5]+sh2[6]+sh2[7])*(1.0f/Cn) + 1e-5f);

    float4 gg = ((const float4*)g)[t];
    float4 bb = ((const float4*)be)[t];
    float r0 = dx*rstd*gg.x + bb.x;
    float r1 = dy*rstd*gg.y + bb.y;
    float r2 = dz*rstd*gg.z + bb.z;
    float r3 = dw*rstd*gg.w + bb.w;
    __half* orow = out + (size_t)row * Cn + (t >> 4) * 64;
    int ca = (4 * t) & 63;
    *(__half2*)(orow + p64(ca))     = __floats2half2_rn(r0, r1);
    *(__half2*)(orow + p64(ca + 2)) = __floats2half2_rn(r2, r3);
}

__global__ void concat3(const float* a, const float* b, const float* c, float* o) {
    int t = blockIdx.x * 256 + threadIdx.x;     // 3072
    o[t] = (t < 1024) ? a[t] : ((t < 2048) ? b[t - 1024] : c[t - 2048]);
}

// ---- all weight transposes: W[K,N] -> Wt[N,K] half, permuted --------------
__global__ void transpose_all(const float* __restrict__ Wq, const float* __restrict__ Wk,
                              const float* __restrict__ Wv, const float* __restrict__ Wo,
                              const float* __restrict__ W1, const float* __restrict__ W2,
                              __half* __restrict__ wtqkv, __half* __restrict__ wto,
                              __half* __restrict__ wt1, __half* __restrict__ wt2) {
    int idx = blockIdx.x;
    const float* W; __half* dst; int K, N, t;
    if (idx < 3072)      { t = idx & 1023; int w = idx >> 10;
                           W = (w==0)?Wq:(w==1)?Wk:Wv; dst = wtqkv + (size_t)w*Cn*Cn;
                           K = Cn; N = Cn; }
    else if (idx < 4096) { t = idx - 3072; W = Wo; dst = wto;  K = Cn;   N = Cn; }
    else if (idx < 8192) { t = idx - 4096; W = W1; dst = wt1;  K = Cn;   N = DFFn; }
    else                 { t = idx - 8192; W = W2; dst = wt2;  K = DFFn; N = Cn; }
    int ntiles = N / 32;
    int n0 = (t % ntiles) * 32, k0 = (t / ntiles) * 32;

    __shared__ float tt[32][33];
    int tx = threadIdx.x, ty = threadIdx.y;     // 32 x 8
    #pragma unroll
    for (int i = 0; i < 32; i += 8)
        tt[ty + i][tx] = W[(size_t)(k0 + ty + i) * N + n0 + tx];
    __syncthreads();
    int kk = k0 + tx;
    int kperm = (kk & ~63) + p64(kk & 63);
    #pragma unroll
    for (int i = 0; i < 32; i += 8)
        dst[(size_t)(n0 + ty + i) * K + kperm] = __float2half_rn(tt[tx][ty + i]);
}

// ---------------- fp16 mma GEMM: 128x256 tile, warp tile 64x64 -------------
// (round-11 config, at legacy-HMMA HW rate)
// OUTM: 0 = fp32 plain, 1 = half permuted, 2 = half plain
#define GBM 128
#define GBN 256
#define GSMEM 147456

template<bool RELU, bool RES, int OUTM>
__global__ __launch_bounds__(256, 1) void gemm_h(
        const __half* __restrict__ A, const __half* __restrict__ Bt,
        const float* __restrict__ bias, const float* __restrict__ res,
        void* __restrict__ CoutV, int M, int N, int K) {
    extern __shared__ __half smh[];
    const int tid = threadIdx.x;
    const int lane = tid & 31;
    const int wid = tid >> 5;
    const int g = lane >> 2, t4 = lane & 3;
    const int wm = wid >> 2, wn = wid & 3;       // 2 x 4 warps, warp tile 64x64
    const int bm = blockIdx.y * GBM;
    const int bn = blockIdx.x * GBN;

    float acc[4][8][4];
    #pragma unroll
    for (int i = 0; i < 4; i++)
        #pragma unroll
        for (int j = 0; j < 8; j++)
            #pragma unroll
            for (int p = 0; p < 4; p++) acc[i][j][p] = 0.0f;

    const uint32_t sm0 = smem_u32(smh);

    auto load_chunk = [&](int c, int s) {
        const uint32_t sA = sm0 + s * 49152;
        const uint32_t sB = sA + 16384;
        const int kc = c * 64;
        const int r = tid >> 3, u = tid & 7;
        const uint32_t du = (uint32_t)(u ^ (r & 7)) * 16;
        #pragma unroll
        for (int j = 0; j < 4; j++) {
            int rr = r + j * 32;
            CP16(sA + rr * 128 + du, A  + (size_t)(bm + rr) * K + kc + u * 8);
        }
        #pragma unroll
        for (int j = 0; j < 8; j++) {
            int rr = r + j * 32;
            CP16(sB + rr * 128 + du, Bt + (size_t)(bn + rr) * K + kc + u * 8);
        }
    };

    load_chunk(0, 0); CPCOMMIT();
    load_chunk(1, 1); CPCOMMIT();

    const int nc = K >> 6;
    int stg = 0;
    for (int c = 0; c < nc; c++) {
        CPWAIT1();
        __syncthreads();
        if (c + 2 < nc) load_chunk(c + 2, (stg + 2) % 3);
        CPCOMMIT();

        const __half* stA = smh + stg * 24576;
        const __half* stB = stA + 8192;
        #pragma unroll
        for (int kp = 0; kp < 2; kp++) {
            const int uoff = ((2*t4 + kp) ^ g) << 3;
            uint4 Ar[4][2];
            uint4 Br[8];
            #pragma unroll
            for (int im = 0; im < 4; im++) {
                int r = wm*64 + im*16 + g;
                Ar[im][0] = *(const uint4*)(stA + r*64 + uoff);
                Ar[im][1] = *(const uint4*)(stA + (r+8)*64 + uoff);
            }
            #pragma unroll
            for (int in_ = 0; in_ < 8; in_++) {
                int n0 = wn*64 + in_*8 + g;
                Br[in_] = *(const uint4*)(stB + n0*64 + uoff);
            }
            #pragma unroll
            for (int sp = 0; sp < 2; sp++) {
                #pragma unroll
                for (int im = 0; im < 4; im++) {
                    uint32_t a0 = sp ? Ar[im][0].z : Ar[im][0].x;
                    uint32_t a1 = sp ? Ar[im][1].z : Ar[im][1].x;
                    uint32_t a2 = sp ? Ar[im][0].w : Ar[im][0].y;
                    uint32_t a3 = sp ? Ar[im][1].w : Ar[im][1].y;
                    #pragma unroll
                    for (int in_ = 0; in_ < 8; in_++) {
                        uint32_t b0 = sp ? Br[in_].z : Br[in_].x;
                        uint32_t b1 = sp ? Br[in_].w : Br[in_].y;
                        mma16(acc[im][in_], a0, a1, a2, a3, b0, b1);
                    }
                }
            }
        }
        stg = (stg + 1) % 3;
    }

    #pragma unroll
    for (int im = 0; im < 4; im++) {
        #pragma unroll
        for (int in_ = 0; in_ < 8; in_++) {
            const float* av = acc[im][in_];
            int r0 = bm + wm*64 + im*16 + g;
            int c0 = bn + wn*64 + in_*8 + t4*2;
            float b0 = bias[c0], b1 = bias[c0 + 1];
            #pragma unroll
            for (int h = 0; h < 2; h++) {
                int row = r0 + h * 8;
                float v0 = av[h*2 + 0] + b0;
                float v1 = av[h*2 + 1] + b1;
                if (RELU) { v0 = fmaxf(v0, 0.f); v1 = fmaxf(v1, 0.f); }
                if (RES) {
                    const float2 rr = *(const float2*)(res + (size_t)row * N + c0);
                    v0 += rr.x; v1 += rr.y;
                }
                if (OUTM == 1) {
                    int c64 = in_*8 + t4*2;
                    __half* dr = (__half*)CoutV + (size_t)row * N + bn + wn*64;
                    *(__half2*)(dr + p64(c64)) = __floats2half2_rn(v0, v1);
                } else if (OUTM == 2) {
                    __half* dr = (__half*)CoutV + (size_t)row * N + c0;
                    *(__half2*)dr = __floats2half2_rn(v0, v1);
                } else {
                    *(float2*)((float*)CoutV + (size_t)row * N + c0) = make_float2(v0, v1);
                }
            }
        }
    }
}

// ---------------- flash attention: software-pipelined S-mma ----------------
// S(kt+1) computed during softmax(kt)+PV(kt). 4-stage K/V ring.
// smem: Q 8KB + 4 x 16KB = 72KB; 3 CTAs/SM.
#define ASMEM 73728

__global__ __launch_bounds__(128, 3) void attn_mma(
        const __half* __restrict__ qkvh, __half* __restrict__ Y) {
    extern __shared__ __align__(16) char asmem[];
    const int qt = (int)gridDim.x - 1 - (int)blockIdx.x;   // LPT: longest first
    const int bh = blockIdx.y;
    const int b = bh >> 4, h = bh & 15;
    const int tid = threadIdx.x;
    const int lane = tid & 31, w = tid >> 5;
    const int g = lane >> 2, t4 = lane & 3;

    const uint32_t sQ = smem_u32(asmem);
    const size_t ldr = 3 * Cn;

    auto load_kv = [&](int kt, int s) {
        uint32_t sK = sQ + 8192 + s * 16384;
        uint32_t sV = sK + 8192;
        int r = tid >> 1, u0 = (tid & 1) * 4;
        const __half* ksrc = qkvh + (size_t)(b*Tn + kt*64 + r) * ldr + Cn + h*HSn;
        const __half* vsrc = ksrc + Cn;
        #pragma unroll
        for (int i = 0; i < 4; i++) {
            int u = u0 + i;
            uint32_t du = (uint32_t)(u ^ (r & 7)) << 4;
            CP16(sK + r*128 + du, ksrc + u*8);
            CP16(sV + r*128 + du, vsrc + u*8);
        }
    };

    // prologue: Q+T0 | T1 | T2 (3 groups, commits unconditional)
    {
        int r = tid >> 1, u0 = (tid & 1) * 4;
        const __half* src = qkvh + (size_t)(b*Tn + qt*64 + r) * ldr + h*HSn;
        #pragma unroll
        for (int i = 0; i < 4; i++) {
            int u = u0 + i;
            CP16(sQ + r*128 + ((u ^ (r & 7)) << 4), src + u*8);
        }
    }
    load_kv(0, 0);
    CPCOMMIT();
    if (qt >= 1) load_kv(1, 1);
    CPCOMMIT();
    if (qt >= 2) load_kv(2, 2);
    CPCOMMIT();
    CPWAIT2();                                   // group0 (Q + T0) done
    __syncthreads();

    // ---- Q frags, scaled by log2(e)/8
    uint32_t qa[4][4];
    {
        int row16 = lane & 15, selq = lane >> 4;
        int qrow = w*16 + row16;
        uint32_t base = sQ + qrow*128;
        int sw = qrow & 7;
        #pragma unroll
        for (int kc = 0; kc < 4; kc++)
            ldsm4(qa[kc][0], qa[kc][1], qa[kc][2], qa[kc][3],
                  base + (((2*kc + selq) ^ sw) << 4));
        __half2 sc = __floats2half2_rn(0.1803368802f, 0.1803368802f);
        #pragma unroll
        for (int kc = 0; kc < 4; kc++)
            #pragma unroll
            for (int i = 0; i < 4; i++) {
                __half2 v = __hmul2(*(__half2*)&qa[kc][i], sc);
                qa[kc][i] = *(uint32_t*)&v;
            }
    }

    const int sel = lane >> 3, subl = lane & 7;
    const int krow0 = (sel >> 1)*8 + subl;
    const int ksw = krow0 & 7, kub = sel & 1;
    const int vrow0 = (sel & 1)*8 + subl;
    const int vsw = vrow0 & 7, vus = sel >> 1;

    // S = Q K^T for one tile (stage s) into sacc
    auto computeS = [&](float (*sacc)[4], int s) {
        const uint32_t sK = sQ + 8192 + s * 16384;
        #pragma unroll
        for (int j = 0; j < 8; j++)
            #pragma unroll
            for (int i = 0; i < 4; i++) sacc[j][i] = 0.0f;
        #pragma unroll
        for (int kc = 0; kc < 4; kc++) {
            #pragma unroll
            for (int jj = 0; jj < 4; jj++) {
                uint32_t b0, b1, b2, b3;
                ldsm4(b0, b1, b2, b3,
                      sK + (16*jj + krow0)*128 + (((2*kc + kub) ^ ksw) << 4));
                mma16(sacc[2*jj],   qa[kc][0], qa[kc][1], qa[kc][2], qa[kc][3], b0, b1);
                mma16(sacc[2*jj+1], qa[kc][0], qa[kc][1], qa[kc][2], qa[kc][3], b2, b3);
            }
        }
    };

    float oacc[8][4];
    #pragma unroll
    for (int t = 0; t < 8; t++)
        #pragma unroll
        for (int i = 0; i < 4; i++) oacc[t][i] = 0.0f;
    float m0 = -1e30f, m1 = -1e30f, l0 = 0.0f, l1 = 0.0f;
    const int rw0 = w*16 + g;

    float sacc[8][4], snext[8][4];
    computeS(sacc, 0);                           // S(0)

    for (int kt = 0; kt <= qt; kt++) {
        // ---- causal mask on diagonal tile (values of tile kt)
        if (kt == qt) {
            #pragma unroll
            for (int j = 0; j < 8; j++) {
                int c0 = 8*j + 2*t4;
                if (c0     > rw0)     sacc[j][0] = -1e30f;
                if (c0 + 1 > rw0)     sacc[j][1] = -1e30f;
                if (c0     > rw0 + 8) sacc[j][2] = -1e30f;
                if (c0 + 1 > rw0 + 8) sacc[j][3] = -1e30f;
            }
        }

        // ---- base-2 online softmax on sacc (tile kt)
        float mx0 = -1e30f, mx1 = -1e30f;
        #pragma unroll
        for (int j = 0; j < 8; j++) {
            mx0 = fmaxf(mx0, fmaxf(sacc[j][0], sacc[j][1]));
            mx1 = fmaxf(mx1, fmaxf(sacc[j][2], sacc[j][3]));
        }
        mx0 = fmaxf(mx0, __shfl_xor_sync(0xffffffffu, mx0, 1));
        mx0 = fmaxf(mx0, __shfl_xor_sync(0xffffffffu, mx0, 2));
        mx1 = fmaxf(mx1, __shfl_xor_sync(0xffffffffu, mx1, 1));
        mx1 = fmaxf(mx1, __shfl_xor_sync(0xffffffffu, mx1, 2));
        float mn0 = fmaxf(m0, mx0), mn1 = fmaxf(m1, mx1);
        float f0 = ex2f(m0 - mn0), f1 = ex2f(m1 - mn1);
        m0 = mn0; m1 = mn1;
        l0 *= f0; l1 *= f1;
        #pragma unroll
        for (int t = 0; t < 8; t++) {
            oacc[t][0] *= f0; oacc[t][1] *= f0;
            oacc[t][2] *= f1; oacc[t][3] *= f1;
        }

        uint32_t pa[8][2];
        #pragma unroll
        for (int j = 0; j < 8; j++) {
            float p00 = ex2f(sacc[j][0] - m0), p01 = ex2f(sacc[j][1] - m0);
            float p10 = ex2f(sacc[j][2] - m1), p11 = ex2f(sacc[j][3] - m1);
            __half2 ha = __floats2half2_rn(p00, p01);
            __half2 hb = __floats2half2_rn(p10, p11);
            float2 fa = __half22float2(ha), fb = __half22float2(hb);
            l0 += fa.x + fa.y; l1 += fb.x + fb.y;
            pa[j][0] = *(uint32_t*)&ha;
            pa[j][1] = *(uint32_t*)&hb;
        }

        // ---- pipelined S(kt+1): overlaps PV below on the tensor pipe
        if (kt < qt) {
            CPWAIT1();                           // tile kt+1 complete (this thread)
            __syncthreads();                     // visible to all warps
            if (kt + 3 <= qt) load_kv(kt + 3, (kt + 3) & 3);
            CPCOMMIT();                          // unconditional group
            computeS(snext, (kt + 1) & 3);
        }

        // ---- O += P V (tile kt)
        const uint32_t sV = sQ + 8192 + (kt & 3) * 16384 + 8192;
        #pragma unroll
        for (int kc = 0; kc < 4; kc++) {
            uint32_t a0 = pa[2*kc][0], a1 = pa[2*kc][1];
            uint32_t a2 = pa[2*kc+1][0], a3 = pa[2*kc+1][1];
            #pragma unroll
            for (int jj = 0; jj < 4; jj++) {
                uint32_t b0, b1, b2, b3;
                ldsm4t(b0, b1, b2, b3,
                       sV + (16*kc + vrow0)*128 + (((2*jj + vus) ^ vsw) << 4));
                mma16(oacc[2*jj],   a0, a1, a2, a3, b0, b1);
                mma16(oacc[2*jj+1], a0, a1, a2, a3, b2, b3);
            }
        }

        if (kt < qt) {
            #pragma unroll
            for (int j = 0; j < 8; j++)
                #pragma unroll
                for (int i = 0; i < 4; i++) sacc[j][i] = snext[j][i];
        }
    }

    l0 += __shfl_xor_sync(0xffffffffu, l0, 1);
    l0 += __shfl_xor_sync(0xffffffffu, l0, 2);
    l1 += __shfl_xor_sync(0xffffffffu, l1, 1);
    l1 += __shfl_xor_sync(0xffffffffu, l1, 2);

    float i0 = 1.0f / l0, i1 = 1.0f / l1;
    const size_t orow0 = (size_t)(b*Tn + qt*64 + rw0) * Cn + h*HSn;
    const size_t orow1 = orow0 + (size_t)8 * Cn;
    #pragma unroll
    for (int t = 0; t < 8; t++) {
        int pp = p64(8*t + 2*t4);
        *(__half2*)(Y + orow0 + pp) = __floats2half2_rn(oacc[t][0]*i0, oacc[t][1]*i0);
        *(__half2*)(Y + orow1 + pp) = __floats2half2_rn(oacc[t][2]*i1, oacc[t][3]*i1);
    }
}

// ---------------- launch ----------------------------------------------------
extern "C" void kernel_launch(void* const* d_in, const int* in_sizes, int n_in,
                              void* d_out, int out_size) {
    const float* x   = (const float*)d_in[0];
    const float* Wq  = (const float*)d_in[1];
    const float* bq  = (const float*)d_in[2];
    const float* Wk  = (const float*)d_in[3];
    const float* bk  = (const float*)d_in[4];
    const float* Wv  = (const float*)d_in[5];
    const float* bv  = (const float*)d_in[6];
    const float* Wo  = (const float*)d_in[7];
    const float* bo  = (const float*)d_in[8];
    const float* W1  = (const float*)d_in[9];
    const float* b1  = (const float*)d_in[10];
    const float* W2  = (const float*)d_in[11];
    const float* b2  = (const float*)d_in[12];
    const float* g1  = (const float*)d_in[13];
    const float* be1 = (const float*)d_in[14];
    const float* g2  = (const float*)d_in[15];
    const float* be2 = (const float*)d_in[16];
    float* out = (float*)d_out;

    __half *buf0, *qkv, *ff, *wtqkv, *wto, *wt1, *wt2;
    float *x2, *bqkv;
    cudaGetSymbolAddress((void**)&buf0,  g_buf0);
    cudaGetSymbolAddress((void**)&qkv,   g_qkv);
    cudaGetSymbolAddress((void**)&x2,    g_x2);
    cudaGetSymbolAddress((void**)&ff,    g_ff);
    cudaGetSymbolAddress((void**)&wtqkv, g_wtqkv);
    cudaGetSymbolAddress((void**)&wto,   g_wto);
    cudaGetSymbolAddress((void**)&wt1,   g_wt1);
    cudaGetSymbolAddress((void**)&wt2,   g_wt2);
    cudaGetSymbolAddress((void**)&bqkv,  g_bqkv);

    cudaFuncSetAttribute(gemm_h<false,false,2>, cudaFuncAttributeMaxDynamicSharedMemorySize, GSMEM);
    cudaFuncSetAttribute(gemm_h<false,true ,0>, cudaFuncAttributeMaxDynamicSharedMemorySize, GSMEM);
    cudaFuncSetAttribute(gemm_h<true ,false,1>, cudaFuncAttributeMaxDynamicSharedMemorySize, GSMEM);
    cudaFuncSetAttribute(attn_mma, cudaFuncAttributeMaxDynamicSharedMemorySize, ASMEM);

    // L1: weight transposes (half, permuted)
    transpose_all<<<12288, dim3(32, 8)>>>(Wq, Wk, Wv, Wo, W1, W2,
                                          wtqkv, wto, wt1, wt2);
    // L2: ln1 (half permuted)
    ln_kernel<<<Mn, 256>>>(x, g1, be1, buf0);
    // L3: qkv bias concat (tiny)
    concat3<<<12, 256>>>(bq, bk, bv, bqkv);

    // L4: merged qkv = ln1 @ [Wq|Wk|Wv] + b -> half PLAIN  (ncu capture slot)
    gemm_h<false,false,2><<<dim3(3*Cn/GBN, Mn/GBM), 256, GSMEM>>>(
        buf0, wtqkv, bqkv, nullptr, qkv, Mn, 3*Cn, Cn);

    // L5: pipelined tensor-core attention -> buf0 (half permuted)
    attn_mma<<<dim3(Tn/64, Bn*Hn), 128, ASMEM>>>(qkv, buf0);

    // L6: x2 = x + y @ Wo + bo   (fp32 plain)
    gemm_h<false,true,0><<<dim3(Cn/GBN, Mn/GBM), 256, GSMEM>>>(
        buf0, wto, bo, x, x2, Mn, Cn, Cn);

    // L7: ln2 -> buf0 (half permuted)
    ln_kernel<<<Mn, 256>>>(x2, g2, be2, buf0);

    // L8: ff = relu(h @ W1 + b1)  (half permuted)
    gemm_h<true,false,1><<<dim3(DFFn/GBN, Mn/GBM), 256, GSMEM>>>(
        buf0, wt1, b1, nullptr, ff, Mn, DFFn, Cn);

    // L9: out = x2 + ff @ W2 + b2  (fp32 plain)
    gemm_h<false,true,0><<<dim3(Cn/GBN, Mn/GBM), 256, GSMEM>>>(
        ff, wt2, b2, x2, out, Mn, Cn, DFFn);
}

// round 15
// speedup vs baseline: 1.0203x; 1.0203x over previous
#include <cuda_runtime.h>
#include <cuda_fp16.h>
#include <cstdint>
#include <math.h>

// ---------------- problem constants ----------------
#define Bn   4
#define Tn   2048
#define Cn   1024
#define Hn   16
#define HSn  64
#define DFFn 4096
#define Mn   (Bn*Tn)          // 8192

// GEMM-operand layout: __half, K-major, each 64-half K-chunk p64-permuted.

// ---------------- scratch (__device__ globals; allocation-free) ------------
__device__ __half g_buf0[(size_t)Mn*Cn];        // ln1 / attn-y / ln2 (half, permuted)
__device__ __half g_qkv [(size_t)Mn*3*Cn];      // merged q|k|v (half, PLAIN)
__device__ float  g_x2  [(size_t)Mn*Cn];        // x + attn (fp32, plain)
__device__ __half g_ff  [(size_t)Mn*DFFn];      // relu(h@W1+b1) (half, permuted)
__device__ __half g_wtqkv[(size_t)3*Cn*Cn];     // (Wq|Wk|Wv)^T (half, permuted)
__device__ __half g_wto [(size_t)Cn*Cn];        // Wo^T
__device__ __half g_wt1 [(size_t)DFFn*Cn];      // W1^T
__device__ __half g_wt2 [(size_t)Cn*DFFn];      // W2^T
__device__ float  g_bqkv[3*Cn];

// ---------------- helpers ----------------
__device__ __forceinline__ uint32_t smem_u32(const void* p) {
    uint32_t a;
    asm("{ .reg .u64 t; cvta.to.shared.u64 t, %1; cvt.u32.u64 %0, t; }" : "=r"(a) : "l"(p));
    return a;
}
__device__ __forceinline__ int p64(int c) {
    int ks = c >> 4, cc = c & 15;
    int kp = ks >> 1, sp = ks & 1;
    int t4 = (cc >> 1) & 3, hi = (cc >> 3) & 1, j = c & 1;
    return (2*t4 + kp)*8 + sp*4 + hi*2 + j;
}
__device__ __forceinline__ float ex2f(float x) {
    float r; asm("ex2.approx.f32 %0, %1;" : "=f"(r) : "f"(x)); return r;
}

#define CP16(dst, src) \
    asm volatile("cp.async.cg.shared.global [%0], [%1], 16;" :: "r"(dst), "l"(src))
#define CPCOMMIT() asm volatile("cp.async.commit_group;")
#define CPWAIT1()  asm volatile("cp.async.wait_group 1;" ::: "memory")
#define CPWAIT0()  asm volatile("cp.async.wait_group 0;" ::: "memory")

__device__ __forceinline__ void mma16(float* d, uint32_t a0, uint32_t a1,
                                      uint32_t a2, uint32_t a3,
                                      uint32_t b0, uint32_t b1) {
    asm volatile("mma.sync.aligned.m16n8k16.row.col.f32.f16.f16.f32 "
        "{%0,%1,%2,%3}, {%4,%5,%6,%7}, {%8,%9}, {%0,%1,%2,%3};"
        : "+f"(d[0]), "+f"(d[1]), "+f"(d[2]), "+f"(d[3])
        : "r"(a0), "r"(a1), "r"(a2), "r"(a3), "r"(b0), "r"(b1));
}
__device__ __forceinline__ void ldsm4(uint32_t& r0, uint32_t& r1, uint32_t& r2,
                                      uint32_t& r3, uint32_t a) {
    asm volatile("ldmatrix.sync.aligned.m8n8.x4.shared.b16 {%0,%1,%2,%3}, [%4];"
        : "=r"(r0), "=r"(r1), "=r"(r2), "=r"(r3) : "r"(a));
}
__device__ __forceinline__ void ldsm4t(uint32_t& r0, uint32_t& r1, uint32_t& r2,
                                       uint32_t& r3, uint32_t a) {
    asm volatile("ldmatrix.sync.aligned.m8n8.x4.trans.shared.b16 {%0,%1,%2,%3}, [%4];"
        : "=r"(r0), "=r"(r1), "=r"(r2), "=r"(r3) : "r"(a));
}

// ---------------- LayerNorm -> half permuted --------------------------------
__global__ void ln_kernel(const float* __restrict__ x, const float* __restrict__ g,
                          const float* __restrict__ be, __half* __restrict__ out) {
    __shared__ float sh1[8], sh2[8];
    const int row = blockIdx.x;
    const int t = threadIdx.x;
    float4 v = ((const float4*)(x + (size_t)row * Cn))[t];

    float s = v.x + v.y + v.z + v.w;
    #pragma unroll
    for (int o = 16; o; o >>= 1) s += __shfl_down_sync(0xffffffffu, s, o);
    if ((t & 31) == 0) sh1[t >> 5] = s;
    __syncthreads();
    float mu = (sh1[0]+sh1[1]+sh1[2]+sh1[3]+sh1[4]+sh1[5]+sh1[6]+sh1[7]) * (1.0f/Cn);

    float dx = v.x-mu, dy = v.y-mu, dz = v.z-mu, dw = v.w-mu;
    float ss = dx*dx + dy*dy + dz*dz + dw*dw;
    #pragma unroll
    for (int o = 16; o; o >>= 1) ss += __shfl_down_sync(0xffffffffu, ss, o);
    if ((t & 31) == 0) sh2[t >> 5] = ss;
    __syncthreads();
    float rstd = rsqrtf((sh2[0]+sh2[1]+sh2[2]+sh2[3]+sh2[4]+sh2[5]+sh2[6]+sh2[7])*(1.0f/Cn) + 1e-5f);

    float4 gg = ((const float4*)g)[t];
    float4 bb = ((const float4*)be)[t];
    float r0 = dx*rstd*gg.x + bb.x;
    float r1 = dy*rstd*gg.y + bb.y;
    float r2 = dz*rstd*gg.z + bb.z;
    float r3 = dw*rstd*gg.w + bb.w;
    __half* orow = out + (size_t)row * Cn + (t >> 4) * 64;
    int ca = (4 * t) & 63;
    *(__half2*)(orow + p64(ca))     = __floats2half2_rn(r0, r1);
    *(__half2*)(orow + p64(ca + 2)) = __floats2half2_rn(r2, r3);
}

__global__ void concat3(const float* a, const float* b, const float* c, float* o) {
    int t = blockIdx.x * 256 + threadIdx.x;     // 3072
    o[t] = (t < 1024) ? a[t] : ((t < 2048) ? b[t - 1024] : c[t - 2048]);
}

// ---- all weight transposes: W[K,N] -> Wt[N,K] half, permuted --------------
__global__ void transpose_all(const float* __restrict__ Wq, const float* __restrict__ Wk,
                              const float* __restrict__ Wv, const float* __restrict__ Wo,
                              const float* __restrict__ W1, const float* __restrict__ W2,
                              __half* __restrict__ wtqkv, __half* __restrict__ wto,
                              __half* __restrict__ wt1, __half* __restrict__ wt2) {
    int idx = blockIdx.x;
    const float* W; __half* dst; int K, N, t;
    if (idx < 3072)      { t = idx & 1023; int w = idx >> 10;
                           W = (w==0)?Wq:(w==1)?Wk:Wv; dst = wtqkv + (size_t)w*Cn*Cn;
                           K = Cn; N = Cn; }
    else if (idx < 4096) { t = idx - 3072; W = Wo; dst = wto;  K = Cn;   N = Cn; }
    else if (idx < 8192) { t = idx - 4096; W = W1; dst = wt1;  K = Cn;   N = DFFn; }
    else                 { t = idx - 8192; W = W2; dst = wt2;  K = DFFn; N = Cn; }
    int ntiles = N / 32;
    int n0 = (t % ntiles) * 32, k0 = (t / ntiles) * 32;

    __shared__ float tt[32][33];
    int tx = threadIdx.x, ty = threadIdx.y;     // 32 x 8
    #pragma unroll
    for (int i = 0; i < 32; i += 8)
        tt[ty + i][tx] = W[(size_t)(k0 + ty + i) * N + n0 + tx];
    __syncthreads();
    int kk = k0 + tx;
    int kperm = (kk & ~63) + p64(kk & 63);
    #pragma unroll
    for (int i = 0; i < 32; i += 8)
        dst[(size_t)(n0 + ty + i) * K + kperm] = __float2half_rn(tt[tx][ty + i]);
}

// ---------------- fp16 mma GEMM: 128x256 tile, warp tile 64x64 -------------
// (round-11 config, at legacy-HMMA HW rate)
// OUTM: 0 = fp32 plain, 1 = half permuted, 2 = half plain
#define GBM 128
#define GBN 256
#define GSMEM 147456

template<bool RELU, bool RES, int OUTM>
__global__ __launch_bounds__(256, 1) void gemm_h(
        const __half* __restrict__ A, const __half* __restrict__ Bt,
        const float* __restrict__ bias, const float* __restrict__ res,
        void* __restrict__ CoutV, int M, int N, int K) {
    extern __shared__ __half smh[];
    const int tid = threadIdx.x;
    const int lane = tid & 31;
    const int wid = tid >> 5;
    const int g = lane >> 2, t4 = lane & 3;
    const int wm = wid >> 2, wn = wid & 3;
    const int bm = blockIdx.y * GBM;
    const int bn = blockIdx.x * GBN;

    float acc[4][8][4];
    #pragma unroll
    for (int i = 0; i < 4; i++)
        #pragma unroll
        for (int j = 0; j < 8; j++)
            #pragma unroll
            for (int p = 0; p < 4; p++) acc[i][j][p] = 0.0f;

    const uint32_t sm0 = smem_u32(smh);

    auto load_chunk = [&](int c, int s) {
        const uint32_t sA = sm0 + s * 49152;
        const uint32_t sB = sA + 16384;
        const int kc = c * 64;
        const int r = tid >> 3, u = tid & 7;
        const uint32_t du = (uint32_t)(u ^ (r & 7)) * 16;
        #pragma unroll
        for (int j = 0; j < 4; j++) {
            int rr = r + j * 32;
            CP16(sA + rr * 128 + du, A  + (size_t)(bm + rr) * K + kc + u * 8);
        }
        #pragma unroll
        for (int j = 0; j < 8; j++) {
            int rr = r + j * 32;
            CP16(sB + rr * 128 + du, Bt + (size_t)(bn + rr) * K + kc + u * 8);
        }
    };

    load_chunk(0, 0); CPCOMMIT();
    load_chunk(1, 1); CPCOMMIT();

    const int nc = K >> 6;
    int stg = 0;
    for (int c = 0; c < nc; c++) {
        CPWAIT1();
        __syncthreads();
        if (c + 2 < nc) load_chunk(c + 2, (stg + 2) % 3);
        CPCOMMIT();

        const __half* stA = smh + stg * 24576;
        const __half* stB = stA + 8192;
        #pragma unroll
        for (int kp = 0; kp < 2; kp++) {
            const int uoff = ((2*t4 + kp) ^ g) << 3;
            uint4 Ar[4][2];
            uint4 Br[8];
            #pragma unroll
            for (int im = 0; im < 4; im++) {
                int r = wm*64 + im*16 + g;
                Ar[im][0] = *(const uint4*)(stA + r*64 + uoff);
                Ar[im][1] = *(const uint4*)(stA + (r+8)*64 + uoff);
            }
            #pragma unroll
            for (int in_ = 0; in_ < 8; in_++) {
                int n0 = wn*64 + in_*8 + g;
                Br[in_] = *(const uint4*)(stB + n0*64 + uoff);
            }
            #pragma unroll
            for (int sp = 0; sp < 2; sp++) {
                #pragma unroll
                for (int im = 0; im < 4; im++) {
                    uint32_t a0 = sp ? Ar[im][0].z : Ar[im][0].x;
                    uint32_t a1 = sp ? Ar[im][1].z : Ar[im][1].x;
                    uint32_t a2 = sp ? Ar[im][0].w : Ar[im][0].y;
                    uint32_t a3 = sp ? Ar[im][1].w : Ar[im][1].y;
                    #pragma unroll
                    for (int in_ = 0; in_ < 8; in_++) {
                        uint32_t b0 = sp ? Br[in_].z : Br[in_].x;
                        uint32_t b1 = sp ? Br[in_].w : Br[in_].y;
                        mma16(acc[im][in_], a0, a1, a2, a3, b0, b1);
                    }
                }
            }
        }
        stg = (stg + 1) % 3;
    }

    #pragma unroll
    for (int im = 0; im < 4; im++) {
        #pragma unroll
        for (int in_ = 0; in_ < 8; in_++) {
            const float* av = acc[im][in_];
            int r0 = bm + wm*64 + im*16 + g;
            int c0 = bn + wn*64 + in_*8 + t4*2;
            float b0 = bias[c0], b1 = bias[c0 + 1];
            #pragma unroll
            for (int h = 0; h < 2; h++) {
                int row = r0 + h * 8;
                float v0 = av[h*2 + 0] + b0;
                float v1 = av[h*2 + 1] + b1;
                if (RELU) { v0 = fmaxf(v0, 0.f); v1 = fmaxf(v1, 0.f); }
                if (RES) {
                    const float2 rr = *(const float2*)(res + (size_t)row * N + c0);
                    v0 += rr.x; v1 += rr.y;
                }
                if (OUTM == 1) {
                    int c64 = in_*8 + t4*2;
                    __half* dr = (__half*)CoutV + (size_t)row * N + bn + wn*64;
                    *(__half2*)(dr + p64(c64)) = __floats2half2_rn(v0, v1);
                } else if (OUTM == 2) {
                    __half* dr = (__half*)CoutV + (size_t)row * N + c0;
                    *(__half2*)dr = __floats2half2_rn(v0, v1);
                } else {
                    *(float2*)((float*)CoutV + (size_t)row * N + c0) = make_float2(v0, v1);
                }
            }
        }
    }
}

// ---------------- flash attention: 128-row q tile, 8 warps -----------------
// K/V tiles (64 keys) shared by 128 q rows; 3-stage ring; base-2 softmax.
// smem: Q 16KB + 3 x 16KB = 64KB; 2 CTAs/SM.
#define ASMEM 65536

__global__ __launch_bounds__(256, 2) void attn_mma(
        const __half* __restrict__ qkvh, __half* __restrict__ Y) {
    extern __shared__ __align__(16) char asmem[];
    const int qt = (int)gridDim.x - 1 - (int)blockIdx.x;   // LPT: longest first
    const int bh = blockIdx.y;
    const int b = bh >> 4, h = bh & 15;
    const int tid = threadIdx.x;
    const int lane = tid & 31, w = tid >> 5;               // 8 warps
    const int g = lane >> 2, t4 = lane & 3;

    const uint32_t sQ = smem_u32(asmem);
    const size_t ldr = 3 * Cn;

    auto load_kv = [&](int kt, int s) {
        uint32_t sK = sQ + 16384 + s * 16384;
        uint32_t sV = sK + 8192;
        int r = tid >> 2, u0 = (tid & 3) * 2;              // 64 rows, 2 units each
        const __half* ksrc = qkvh + (size_t)(b*Tn + kt*64 + r) * ldr + Cn + h*HSn;
        const __half* vsrc = ksrc + Cn;
        #pragma unroll
        for (int i = 0; i < 2; i++) {
            int u = u0 + i;
            uint32_t du = (uint32_t)(u ^ (r & 7)) << 4;
            CP16(sK + r*128 + du, ksrc + u*8);
            CP16(sV + r*128 + du, vsrc + u*8);
        }
    };

    // prologue: Q (128 rows) + KV0 | KV1
    {
        int r = tid >> 1, u0 = (tid & 1) * 4;              // 128 rows, 4 units each
        const __half* src = qkvh + (size_t)(b*Tn + qt*128 + r) * ldr + h*HSn;
        #pragma unroll
        for (int i = 0; i < 4; i++) {
            int u = u0 + i;
            CP16(sQ + r*128 + ((u ^ (r & 7)) << 4), src + u*8);
        }
    }
    const int ktmax = 2*qt + 1;
    load_kv(0, 0);
    CPCOMMIT();
    load_kv(1, 1);                                          // ktmax >= 1 always
    CPCOMMIT();
    CPWAIT1();
    __syncthreads();

    // ---- Q frags, scaled by log2(e)/8
    uint32_t qa[4][4];
    {
        int row16 = lane & 15, selq = lane >> 4;
        int qrow = w*16 + row16;                            // 0..127
        uint32_t base = sQ + qrow*128;
        int sw = qrow & 7;
        #pragma unroll
        for (int kc = 0; kc < 4; kc++)
            ldsm4(qa[kc][0], qa[kc][1], qa[kc][2], qa[kc][3],
                  base + (((2*kc + selq) ^ sw) << 4));
        __half2 sc = __floats2half2_rn(0.1803368802f, 0.1803368802f);
        #pragma unroll
        for (int kc = 0; kc < 4; kc++)
            #pragma unroll
            for (int i = 0; i < 4; i++) {
                __half2 v = __hmul2(*(__half2*)&qa[kc][i], sc);
                qa[kc][i] = *(uint32_t*)&v;
            }
    }

    float oacc[8][4];
    #pragma unroll
    for (int t = 0; t < 8; t++)
        #pragma unroll
        for (int i = 0; i < 4; i++) oacc[t][i] = 0.0f;
    float m0 = -1e30f, m1 = -1e30f, l0 = 0.0f, l1 = 0.0f;
    const int rowg0 = qt*128 + w*16 + g;                    // global q row (half 0)

    const int sel = lane >> 3, subl = lane & 7;
    const int krow0 = (sel >> 1)*8 + subl;
    const int ksw = krow0 & 7, kub = sel & 1;
    const int vrow0 = (sel & 1)*8 + subl;
    const int vsw = vrow0 & 7, vus = sel >> 1;

    int stg = 0;
    for (int kt = 0; kt <= ktmax; kt++) {
        if (kt > 0) {
            CPWAIT1();
            __syncthreads();
        }
        if (kt + 2 <= ktmax) load_kv(kt + 2, (stg + 2) % 3);
        CPCOMMIT();

        const uint32_t sK = sQ + 16384 + stg * 16384;
        const uint32_t sV = sK + 8192;

        // ---- S = Q K^T
        float sacc[8][4];
        #pragma unroll
        for (int j = 0; j < 8; j++)
            #pragma unroll
            for (int i = 0; i < 4; i++) sacc[j][i] = 0.0f;
        #pragma unroll
        for (int kc = 0; kc < 4; kc++) {
            #pragma unroll
            for (int jj = 0; jj < 4; jj++) {
                uint32_t b0, b1, b2, b3;
                ldsm4(b0, b1, b2, b3,
                      sK + (16*jj + krow0)*128 + (((2*kc + kub) ^ ksw) << 4));
                mma16(sacc[2*jj],   qa[kc][0], qa[kc][1], qa[kc][2], qa[kc][3], b0, b1);
                mma16(sacc[2*jj+1], qa[kc][0], qa[kc][1], qa[kc][2], qa[kc][3], b2, b3);
            }
        }

        // ---- causal mask (only possible on the last two tiles)
        if (kt >= 2*qt) {
            const int kbase = kt*64;
            #pragma unroll
            for (int j = 0; j < 8; j++) {
                int cg = kbase + 8*j + 2*t4;
                if (cg     > rowg0)      sacc[j][0] = -1e30f;
                if (cg + 1 > rowg0)      sacc[j][1] = -1e30f;
                if (cg     > rowg0 + 8)  sacc[j][2] = -1e30f;
                if (cg + 1 > rowg0 + 8)  sacc[j][3] = -1e30f;
            }
        }

        // ---- base-2 online softmax (m reduced across quad)
        float mx0 = -1e30f, mx1 = -1e30f;
        #pragma unroll
        for (int j = 0; j < 8; j++) {
            mx0 = fmaxf(mx0, fmaxf(sacc[j][0], sacc[j][1]));
            mx1 = fmaxf(mx1, fmaxf(sacc[j][2], sacc[j][3]));
        }
        mx0 = fmaxf(mx0, __shfl_xor_sync(0xffffffffu, mx0, 1));
        mx0 = fmaxf(mx0, __shfl_xor_sync(0xffffffffu, mx0, 2));
        mx1 = fmaxf(mx1, __shfl_xor_sync(0xffffffffu, mx1, 1));
        mx1 = fmaxf(mx1, __shfl_xor_sync(0xffffffffu, mx1, 2));
        float mn0 = fmaxf(m0, mx0), mn1 = fmaxf(m1, mx1);
        float f0 = ex2f(m0 - mn0), f1 = ex2f(m1 - mn1);
        m0 = mn0; m1 = mn1;
        l0 *= f0; l1 *= f1;
        #pragma unroll
        for (int t = 0; t < 8; t++) {
            oacc[t][0] *= f0; oacc[t][1] *= f0;
            oacc[t][2] *= f1; oacc[t][3] *= f1;
        }

        uint32_t pa[8][2];
        #pragma unroll
        for (int j = 0; j < 8; j++) {
            float p00 = ex2f(sacc[j][0] - m0), p01 = ex2f(sacc[j][1] - m0);
            float p10 = ex2f(sacc[j][2] - m1), p11 = ex2f(sacc[j][3] - m1);
            __half2 ha = __floats2half2_rn(p00, p01);
            __half2 hb = __floats2half2_rn(p10, p11);
            float2 fa = __half22float2(ha), fb = __half22float2(hb);
            l0 += fa.x + fa.y; l1 += fb.x + fb.y;
            pa[j][0] = *(uint32_t*)&ha;
            pa[j][1] = *(uint32_t*)&hb;
        }

        // ---- O += P V
        #pragma unroll
        for (int kc = 0; kc < 4; kc++) {
            uint32_t a0 = pa[2*kc][0], a1 = pa[2*kc][1];
            uint32_t a2 = pa[2*kc+1][0], a3 = pa[2*kc+1][1];
            #pragma unroll
            for (int jj = 0; jj < 4; jj++) {
                uint32_t b0, b1, b2, b3;
                ldsm4t(b0, b1, b2, b3,
                       sV + (16*kc + vrow0)*128 + (((2*jj + vus) ^ vsw) << 4));
                mma16(oacc[2*jj],   a0, a1, a2, a3, b0, b1);
                mma16(oacc[2*jj+1], a0, a1, a2, a3, b2, b3);
            }
        }
        stg = (stg + 1) % 3;
    }

    // ---- reduce partial l across the t4 quad (m already shared)
    l0 += __shfl_xor_sync(0xffffffffu, l0, 1);
    l0 += __shfl_xor_sync(0xffffffffu, l0, 2);
    l1 += __shfl_xor_sync(0xffffffffu, l1, 1);
    l1 += __shfl_xor_sync(0xffffffffu, l1, 2);

    // ---- normalize + write permuted half
    float i0 = 1.0f / l0, i1 = 1.0f / l1;
    const size_t orow0 = (size_t)(b*Tn + rowg0) * Cn + h*HSn;
    const size_t orow1 = orow0 + (size_t)8 * Cn;
    #pragma unroll
    for (int t = 0; t < 8; t++) {
        int pp = p64(8*t + 2*t4);
        *(__half2*)(Y + orow0 + pp) = __floats2half2_rn(oacc[t][0]*i0, oacc[t][1]*i0);
        *(__half2*)(Y + orow1 + pp) = __floats2half2_rn(oacc[t][2]*i1, oacc[t][3]*i1);
    }
}

// ---------------- launch ----------------------------------------------------
extern "C" void kernel_launch(void* const* d_in, const int* in_sizes, int n_in,
                              void* d_out, int out_size) {
    const float* x   = (const float*)d_in[0];
    const float* Wq  = (const float*)d_in[1];
    const float* bq  = (const float*)d_in[2];
    const float* Wk  = (const float*)d_in[3];
    const float* bk  = (const float*)d_in[4];
    const float* Wv  = (const float*)d_in[5];
    const float* bv  = (const float*)d_in[6];
    const float* Wo  = (const float*)d_in[7];
    const float* bo  = (const float*)d_in[8];
    const float* W1  = (const float*)d_in[9];
    const float* b1  = (const float*)d_in[10];
    const float* W2  = (const float*)d_in[11];
    const float* b2  = (const float*)d_in[12];
    const float* g1  = (const float*)d_in[13];
    const float* be1 = (const float*)d_in[14];
    const float* g2  = (const float*)d_in[15];
    const float* be2 = (const float*)d_in[16];
    float* out = (float*)d_out;

    __half *buf0, *qkv, *ff, *wtqkv, *wto, *wt1, *wt2;
    float *x2, *bqkv;
    cudaGetSymbolAddress((void**)&buf0,  g_buf0);
    cudaGetSymbolAddress((void**)&qkv,   g_qkv);
    cudaGetSymbolAddress((void**)&x2,    g_x2);
    cudaGetSymbolAddress((void**)&ff,    g_ff);
    cudaGetSymbolAddress((void**)&wtqkv, g_wtqkv);
    cudaGetSymbolAddress((void**)&wto,   g_wto);
    cudaGetSymbolAddress((void**)&wt1,   g_wt1);
    cudaGetSymbolAddress((void**)&wt2,   g_wt2);
    cudaGetSymbolAddress((void**)&bqkv,  g_bqkv);

    cudaFuncSetAttribute(gemm_h<false,false,2>, cudaFuncAttributeMaxDynamicSharedMemorySize, GSMEM);
    cudaFuncSetAttribute(gemm_h<false,true ,0>, cudaFuncAttributeMaxDynamicSharedMemorySize, GSMEM);
    cudaFuncSetAttribute(gemm_h<true ,false,1>, cudaFuncAttributeMaxDynamicSharedMemorySize, GSMEM);
    cudaFuncSetAttribute(attn_mma, cudaFuncAttributeMaxDynamicSharedMemorySize, ASMEM);

    // L1: weight transposes (half, permuted)
    transpose_all<<<12288, dim3(32, 8)>>>(Wq, Wk, Wv, Wo, W1, W2,
                                          wtqkv, wto, wt1, wt2);
    // L2: ln1 (half permuted)
    ln_kernel<<<Mn, 256>>>(x, g1, be1, buf0);
    // L3: qkv bias concat (tiny)
    concat3<<<12, 256>>>(bq, bk, bv, bqkv);

    // L4: merged qkv = ln1 @ [Wq|Wk|Wv] + b -> half PLAIN  (ncu capture slot)
    gemm_h<false,false,2><<<dim3(3*Cn/GBN, Mn/GBM), 256, GSMEM>>>(
        buf0, wtqkv, bqkv, nullptr, qkv, Mn, 3*Cn, Cn);

    // L5: attention, 128-row q tiles -> buf0 (half permuted)
    attn_mma<<<dim3(Tn/128, Bn*Hn), 256, ASMEM>>>(qkv, buf0);

    // L6: x2 = x + y @ Wo + bo   (fp32 plain)
    gemm_h<false,true,0><<<dim3(Cn/GBN, Mn/GBM), 256, GSMEM>>>(
        buf0, wto, bo, x, x2, Mn, Cn, Cn);

    // L7: ln2 -> buf0 (half permuted)
    ln_kernel<<<Mn, 256>>>(x2, g2, be2, buf0);

    // L8: ff = relu(h @ W1 + b1)  (half permuted)
    gemm_h<true,false,1><<<dim3(DFFn/GBN, Mn/GBM), 256, GSMEM>>>(
        buf0, wt1, b1, nullptr, ff, Mn, DFFn, Cn);

    // L9: out = x2 + ff @ W2 + b2  (fp32 plain)
    gemm_h<false,true,0><<<dim3(Cn/GBN, Mn/GBM), 256, GSMEM>>>(
        ff, wt2, b2, x2, out, Mn, Cn, DFFn);
}